// round 3
// baseline (speedup 1.0000x reference)
#include <cuda_runtime.h>

// Problem shape (fixed by dataset): B=32, T=256, D=512, P=20
#define BB 32
#define TT 256
#define DD 512
#define PP 20
#define EPSF 1e-12f

// ---------------- scratch (static device allocations are allowed) ----------
__device__ float g_na[BB * TT * DD];       // 16 MB
__device__ float g_nb[BB * TT * DD];       // 16 MB
__device__ float g_alpha[BB * DD * DD];    // 32 MB
__device__ float g_invn[BB * DD];          // 64 KB
__device__ float g_hmean[BB * TT * DD];    // 16 MB

// ---------------- 1) row l2-normalize both inputs ---------------------------
// grid = 2*B*T blocks, 128 threads; each thread owns one float4 of the row.
__global__ __launch_bounds__(128) void normalize_kernel(
    const float* __restrict__ ia, const float* __restrict__ ib)
{
    int row = blockIdx.x;
    const float* src;
    float* dst;
    if (row < BB * TT) {
        src = ia + (size_t)row * DD;
        dst = g_na + (size_t)row * DD;
    } else {
        int r = row - BB * TT;
        src = ib + (size_t)r * DD;
        dst = g_nb + (size_t)r * DD;
    }
    int tid = threadIdx.x;
    float4 v = ((const float4*)src)[tid];
    float ss = fmaf(v.x, v.x, fmaf(v.y, v.y, fmaf(v.z, v.z, v.w * v.w)));
#pragma unroll
    for (int off = 16; off; off >>= 1)
        ss += __shfl_xor_sync(0xffffffffu, ss, off);
    __shared__ float sp[4];
    if ((tid & 31) == 0) sp[tid >> 5] = ss;
    __syncthreads();
    float tot = sp[0] + sp[1] + sp[2] + sp[3];
    float inv = rsqrtf(fmaxf(tot, EPSF));
    float4 o = make_float4(v.x * inv, v.y * inv, v.z * inv, v.w * inv);
    ((float4*)dst)[tid] = o;
}

// ---------------- 2) alpha[b,d,e] = sum_t nb[b,t,d] * na[b,t,e] -------------
// Per batch: M=512 (d), N=512 (e), K=256 (t). Both operands are K-major in
// global (row = t), so tile loads are directly coalesced.
// Double-buffered smem: one barrier per K-tile, next-tile LDGs issued before
// the FMA block so their latency is hidden under 1024 FMAs/thread.
#define G_BM 128
#define G_BN 128
#define G_BK 16

__global__ __launch_bounds__(256) void gemm_alpha_kernel()
{
    const int b = blockIdx.z;
    const float* A = g_nb + (size_t)b * TT * DD;   // A[k][m], ld = DD
    const float* Bm = g_na + (size_t)b * TT * DD;  // B[k][n], ld = DD
    float* Cb = g_alpha + (size_t)b * DD * DD;

    __shared__ __align__(16) float As[2][G_BK][G_BM];
    __shared__ __align__(16) float Bs[2][G_BK][G_BN];

    const int m0 = blockIdx.y * G_BM;
    const int n0 = blockIdx.x * G_BN;
    const int tid = threadIdx.x;
    const int tx = tid & 15;   // 16 thread-cols
    const int ty = tid >> 4;   // 16 thread-rows

    // per-thread load coordinates (2 float4 per matrix per tile)
    const int kk0 = tid >> 5, mf0 = tid & 31;          // f = tid
    const int kk1 = (tid + 256) >> 5, mf1 = tid & 31;  // f = tid + 256

    float acc[8][8];
#pragma unroll
    for (int i = 0; i < 8; i++)
#pragma unroll
        for (int j = 0; j < 8; j++) acc[i][j] = 0.f;

    // prologue: tile 0 -> buffer 0
    {
        *(float4*)&As[0][kk0][mf0 * 4] = *(const float4*)(A + (size_t)kk0 * DD + m0 + mf0 * 4);
        *(float4*)&Bs[0][kk0][mf0 * 4] = *(const float4*)(Bm + (size_t)kk0 * DD + n0 + mf0 * 4);
        *(float4*)&As[0][kk1][mf1 * 4] = *(const float4*)(A + (size_t)kk1 * DD + m0 + mf1 * 4);
        *(float4*)&Bs[0][kk1][mf1 * 4] = *(const float4*)(Bm + (size_t)kk1 * DD + n0 + mf1 * 4);
    }
    __syncthreads();

    int buf = 0;
    for (int k0 = 0; k0 < TT; k0 += G_BK) {
        const int kn = k0 + G_BK;
        float4 va0, vb0, va1, vb1;
        if (kn < TT) {
            va0 = *(const float4*)(A + (size_t)(kn + kk0) * DD + m0 + mf0 * 4);
            vb0 = *(const float4*)(Bm + (size_t)(kn + kk0) * DD + n0 + mf0 * 4);
            va1 = *(const float4*)(A + (size_t)(kn + kk1) * DD + m0 + mf1 * 4);
            vb1 = *(const float4*)(Bm + (size_t)(kn + kk1) * DD + n0 + mf1 * 4);
        }
#pragma unroll
        for (int kk = 0; kk < G_BK; kk++) {
            float a[8], bb[8];
            *(float4*)&a[0] = *(const float4*)&As[buf][kk][ty * 8];
            *(float4*)&a[4] = *(const float4*)&As[buf][kk][ty * 8 + 4];
            *(float4*)&bb[0] = *(const float4*)&Bs[buf][kk][tx * 8];
            *(float4*)&bb[4] = *(const float4*)&Bs[buf][kk][tx * 8 + 4];
#pragma unroll
            for (int i = 0; i < 8; i++)
#pragma unroll
                for (int j = 0; j < 8; j++) acc[i][j] = fmaf(a[i], bb[j], acc[i][j]);
        }
        if (kn < TT) {
            int nb_ = buf ^ 1;
            *(float4*)&As[nb_][kk0][mf0 * 4] = va0;
            *(float4*)&Bs[nb_][kk0][mf0 * 4] = vb0;
            *(float4*)&As[nb_][kk1][mf1 * 4] = va1;
            *(float4*)&Bs[nb_][kk1][mf1 * 4] = vb1;
        }
        __syncthreads();
        buf ^= 1;
    }

#pragma unroll
    for (int i = 0; i < 8; i++) {
        float* crow = Cb + (size_t)(m0 + ty * 8 + i) * DD + n0 + tx * 8;
        *(float4*)&crow[0] = *(float4*)&acc[i][0];
        *(float4*)&crow[4] = *(float4*)&acc[i][4];
    }
}

// ---------------- 3) column norms of alpha over d ---------------------------
// invn[b,e] = 1/sqrt(max(sum_d alpha[b,d,e]^2, eps))
__global__ __launch_bounds__(256) void colnorm_kernel()
{
    int b = blockIdx.y;
    int e0 = blockIdx.x * 64;
    int el = threadIdx.x & 63;
    int dg = threadIdx.x >> 6;
    const float* A = g_alpha + (size_t)b * DD * DD;
    float s = 0.f;
    for (int d = dg; d < DD; d += 4) {
        float v = A[(size_t)d * DD + e0 + el];
        s = fmaf(v, v, s);
    }
    __shared__ float red[4][64];
    red[dg][el] = s;
    __syncthreads();
    if (dg == 0) {
        float tot = red[0][el] + red[1][el] + red[2][el] + red[3][el];
        g_invn[b * DD + e0 + el] = rsqrtf(fmaxf(tot, EPSF));
    }
}

// ---------------- 4) hmean[b,t,e] = sum_d nb[b,t,d] * alpha[b,d,e] * invn[b,e]
// M=256 (t), N=512 (e), K=512 (d). A is M-major -> transpose on load into
// As[BM][BK]. Double-buffered like gemm_alpha.
__global__ __launch_bounds__(256) void gemm_hmean_kernel()
{
    const int b = blockIdx.z;
    const float* A = g_nb + (size_t)b * TT * DD;       // A[m][k], ld = DD
    const float* Bm = g_alpha + (size_t)b * DD * DD;   // B[k][n], ld = DD
    const float* invn = g_invn + b * DD;
    float* Cb = g_hmean + (size_t)b * TT * DD;

    __shared__ __align__(16) float As[2][G_BM][G_BK];
    __shared__ __align__(16) float Bs[2][G_BK][G_BN];

    const int m0 = blockIdx.y * G_BM;
    const int n0 = blockIdx.x * G_BN;
    const int tid = threadIdx.x;
    const int tx = tid & 15;
    const int ty = tid >> 4;

    // A-tile coords: 128 rows x 16 cols = 512 float4 (4 per row)
    const int amm0 = tid >> 2, akf0 = tid & 3;
    const int amm1 = (tid + 256) >> 2, akf1 = tid & 3;
    // B-tile coords
    const int bkk0 = tid >> 5, bmf0 = tid & 31;
    const int bkk1 = (tid + 256) >> 5, bmf1 = tid & 31;

    float acc[8][8];
#pragma unroll
    for (int i = 0; i < 8; i++)
#pragma unroll
        for (int j = 0; j < 8; j++) acc[i][j] = 0.f;

    // prologue: tile 0 -> buffer 0
    {
        *(float4*)&As[0][amm0][akf0 * 4] = *(const float4*)(A + (size_t)(m0 + amm0) * DD + akf0 * 4);
        *(float4*)&As[0][amm1][akf1 * 4] = *(const float4*)(A + (size_t)(m0 + amm1) * DD + akf1 * 4);
        *(float4*)&Bs[0][bkk0][bmf0 * 4] = *(const float4*)(Bm + (size_t)bkk0 * DD + n0 + bmf0 * 4);
        *(float4*)&Bs[0][bkk1][bmf1 * 4] = *(const float4*)(Bm + (size_t)bkk1 * DD + n0 + bmf1 * 4);
    }
    __syncthreads();

    int buf = 0;
    for (int k0 = 0; k0 < DD; k0 += G_BK) {
        const int kn = k0 + G_BK;
        float4 ra0, ra1, rb0, rb1;
        if (kn < DD) {
            ra0 = *(const float4*)(A + (size_t)(m0 + amm0) * DD + kn + akf0 * 4);
            ra1 = *(const float4*)(A + (size_t)(m0 + amm1) * DD + kn + akf1 * 4);
            rb0 = *(const float4*)(Bm + (size_t)(kn + bkk0) * DD + n0 + bmf0 * 4);
            rb1 = *(const float4*)(Bm + (size_t)(kn + bkk1) * DD + n0 + bmf1 * 4);
        }
#pragma unroll
        for (int kk = 0; kk < G_BK; kk++) {
            float a[8], bb[8];
#pragma unroll
            for (int i = 0; i < 8; i++) a[i] = As[buf][ty * 8 + i][kk];  // broadcast
            *(float4*)&bb[0] = *(const float4*)&Bs[buf][kk][tx * 8];
            *(float4*)&bb[4] = *(const float4*)&Bs[buf][kk][tx * 8 + 4];
#pragma unroll
            for (int i = 0; i < 8; i++)
#pragma unroll
                for (int j = 0; j < 8; j++) acc[i][j] = fmaf(a[i], bb[j], acc[i][j]);
        }
        if (kn < DD) {
            int nb_ = buf ^ 1;
            *(float4*)&As[nb_][amm0][akf0 * 4] = ra0;
            *(float4*)&As[nb_][amm1][akf1 * 4] = ra1;
            *(float4*)&Bs[nb_][bkk0][bmf0 * 4] = rb0;
            *(float4*)&Bs[nb_][bkk1][bmf1 * 4] = rb1;
        }
        __syncthreads();
        buf ^= 1;
    }

    float sc[8];
#pragma unroll
    for (int j = 0; j < 8; j++) sc[j] = invn[n0 + tx * 8 + j];
#pragma unroll
    for (int i = 0; i < 8; i++) {
        float out[8];
#pragma unroll
        for (int j = 0; j < 8; j++) out[j] = acc[i][j] * sc[j];
        float* crow = Cb + (size_t)(m0 + ty * 8 + i) * DD + n0 + tx * 8;
        *(float4*)&crow[0] = *(float4*)&out[0];
        *(float4*)&crow[4] = *(float4*)&out[4];
    }
}

// ---------------- 5) perspective matching -----------------------------------
// persp[b,t,p] = s3 / (sqrt(max(s1,eps)) * sqrt(max(s2,eps)))
//   s1 = sum_d (a_d w_pd)^2, s2 = sum_d (h_d w_pd)^2, s3 = sum_d (a_d w_pd)(h_d w_pd)
// One warp per (b,t) row; W staged in shared once per block (8 rows/block).
__global__ __launch_bounds__(256) void persp_kernel(
    const float* __restrict__ inp_a, const float* __restrict__ W,
    float* __restrict__ out, int dup)
{
    __shared__ float sW[PP * DD];   // 40 KB
    int tid = threadIdx.x;
    for (int i = tid; i < PP * DD / 4; i += 256)
        ((float4*)sW)[i] = ((const float4*)W)[i];
    __syncthreads();

    int warp = tid >> 5, lane = tid & 31;
    int bt = blockIdx.x * 8 + warp;   // grid = B*T/8 = 1024

    const float* a = inp_a + (size_t)bt * DD;
    const float* h = g_hmean + (size_t)bt * DD;
    float av[16], hv[16];
#pragma unroll
    for (int i = 0; i < 16; i++) {
        av[i] = a[lane + 32 * i];
        hv[i] = h[lane + 32 * i];
    }

    const int n = BB * TT * PP;
    for (int p = 0; p < PP; p++) {
        float s1 = 0.f, s2 = 0.f, s3 = 0.f;
#pragma unroll
        for (int i = 0; i < 16; i++) {
            float w = sW[p * DD + lane + 32 * i];
            float t1 = w * av[i];
            float t2 = w * hv[i];
            s1 = fmaf(t1, t1, s1);
            s2 = fmaf(t2, t2, s2);
            s3 = fmaf(t1, t2, s3);
        }
#pragma unroll
        for (int off = 16; off; off >>= 1) {
            s1 += __shfl_xor_sync(0xffffffffu, s1, off);
            s2 += __shfl_xor_sync(0xffffffffu, s2, off);
            s3 += __shfl_xor_sync(0xffffffffu, s3, off);
        }
        if (lane == 0) {
            float r = s3 * rsqrtf(fmaxf(s1, EPSF)) * rsqrtf(fmaxf(s2, EPSF));
            int idx = bt * PP + p;
            out[idx] = r;
            if (dup) out[idx + n] = r;
        }
    }
}

// ---------------- launch ----------------------------------------------------
extern "C" void kernel_launch(void* const* d_in, const int* in_sizes, int n_in,
                              void* d_out, int out_size)
{
    const float* inp_a = (const float*)d_in[0];
    const float* inp_b = (const float*)d_in[1];
    const float* W = (const float*)d_in[2];
    float* out = (float*)d_out;

    (void)in_sizes; (void)n_in;

    // 1) normalize both inputs
    normalize_kernel<<<2 * BB * TT, 128>>>(inp_a, inp_b);

    // 2) alpha = nb^T @ na (per batch)
    gemm_alpha_kernel<<<dim3(DD / G_BN, DD / G_BM, BB), 256>>>();

    // 3) column inverse norms of alpha
    colnorm_kernel<<<dim3(DD / 64, BB), 256>>>();

    // 4) hmean = nb @ (alpha * invn)
    gemm_hmean_kernel<<<dim3(DD / G_BN, TT / G_BM, BB), 256>>>();

    // 5) perspective outputs (tuple (persp, persp) -> write twice if room)
    int n = BB * TT * PP;
    int dup = (out_size >= 2 * n) ? 1 : 0;
    persp_kernel<<<BB * TT / 8, 256>>>(inp_a, W, out, dup);
}

// round 7
// speedup vs baseline: 1.2429x; 1.2429x over previous
#include <cuda_runtime.h>

// Problem shape (fixed by dataset): B=32, T=256, D=512, P=20
#define BB 32
#define TT 256
#define DD 512
#define PP 20
#define EPSF 1e-12f

// ---------------- scratch (static device allocations are allowed) ----------
__device__ float g_na[BB * TT * DD];       // 16 MB
__device__ float g_nb[BB * TT * DD];       // 16 MB
__device__ float g_alpha[BB * DD * DD];    // 32 MB
__device__ float g_invn[BB * DD];          // 64 KB
__device__ float g_hmean[BB * TT * DD];    // 16 MB

// ---------------- cp.async helpers ------------------------------------------
__device__ __forceinline__ unsigned su32(const void* p) {
    return (unsigned)__cvta_generic_to_shared(p);
}
#define CP16(dst, src) \
    asm volatile("cp.async.cg.shared.global [%0], [%1], 16;\n" :: "r"(dst), "l"(src))
#define CPCOMMIT() asm volatile("cp.async.commit_group;\n")
#define CPWAIT0()  asm volatile("cp.async.wait_group 0;\n" ::: "memory")

// ---------------- 1) row l2-normalize both inputs ---------------------------
__global__ __launch_bounds__(128) void normalize_kernel(
    const float* __restrict__ ia, const float* __restrict__ ib)
{
    int row = blockIdx.x;
    const float* src;
    float* dst;
    if (row < BB * TT) {
        src = ia + (size_t)row * DD;
        dst = g_na + (size_t)row * DD;
    } else {
        int r = row - BB * TT;
        src = ib + (size_t)r * DD;
        dst = g_nb + (size_t)r * DD;
    }
    int tid = threadIdx.x;
    float4 v = ((const float4*)src)[tid];
    float ss = fmaf(v.x, v.x, fmaf(v.y, v.y, fmaf(v.z, v.z, v.w * v.w)));
#pragma unroll
    for (int off = 16; off; off >>= 1)
        ss += __shfl_xor_sync(0xffffffffu, ss, off);
    __shared__ float sp[4];
    if ((tid & 31) == 0) sp[tid >> 5] = ss;
    __syncthreads();
    float tot = sp[0] + sp[1] + sp[2] + sp[3];
    float inv = rsqrtf(fmaxf(tot, EPSF));
    float4 o = make_float4(v.x * inv, v.y * inv, v.z * inv, v.w * inv);
    ((float4*)dst)[tid] = o;
}

// ---------------- 2) alpha[b,d,e] = sum_t nb[b,t,d] * na[b,t,e] -------------
// M=512 (d), N=512 (e), K=256 (t). Both operands K-major -> coalesced tiles.
// Double-buffered smem fed by cp.async (no register staging), 2 CTAs/SM.
#define G_BM 128
#define G_BN 128
#define G_BK 16

__global__ __launch_bounds__(256, 2) void gemm_alpha_kernel()
{
    const int b = blockIdx.z;
    const float* A = g_nb + (size_t)b * TT * DD;   // A[k][m], ld = DD
    const float* Bm = g_na + (size_t)b * TT * DD;  // B[k][n], ld = DD
    float* Cb = g_alpha + (size_t)b * DD * DD;

    __shared__ __align__(16) float As[2][G_BK][G_BM];
    __shared__ __align__(16) float Bs[2][G_BK][G_BN];

    const int m0 = blockIdx.y * G_BM;
    const int n0 = blockIdx.x * G_BN;
    const int tid = threadIdx.x;
    const int tx = tid & 15;   // 16 thread-cols
    const int ty = tid >> 4;   // 16 thread-rows

    // per-thread load coordinates (2 float4 per matrix per tile)
    const int kk0 = tid >> 5, mf = tid & 31;           // f = tid
    const int kk1 = (tid + 256) >> 5;                  // f = tid + 256

    // global source addresses (advance by G_BK rows each tile)
    const float* ga0 = A + (size_t)kk0 * DD + m0 + mf * 4;
    const float* gb0 = Bm + (size_t)kk0 * DD + n0 + mf * 4;
    const float* ga1 = A + (size_t)kk1 * DD + m0 + mf * 4;
    const float* gb1 = Bm + (size_t)kk1 * DD + n0 + mf * 4;

    unsigned sa[2], sb[2], sa1[2], sb1[2];
#pragma unroll
    for (int s = 0; s < 2; s++) {
        sa[s]  = su32(&As[s][kk0][mf * 4]);
        sb[s]  = su32(&Bs[s][kk0][mf * 4]);
        sa1[s] = su32(&As[s][kk1][mf * 4]);
        sb1[s] = su32(&Bs[s][kk1][mf * 4]);
    }

    float acc[8][8];
#pragma unroll
    for (int i = 0; i < 8; i++)
#pragma unroll
        for (int j = 0; j < 8; j++) acc[i][j] = 0.f;

    // prologue: tile 0 -> buffer 0
    CP16(sa[0], ga0); CP16(sb[0], gb0);
    CP16(sa1[0], ga1); CP16(sb1[0], gb1);
    CPCOMMIT();
    CPWAIT0();
    __syncthreads();

    int buf = 0;
    const int step = G_BK * DD;   // advance K rows
    for (int k0 = 0; k0 < TT; k0 += G_BK) {
        const bool more = (k0 + G_BK) < TT;
        if (more) {
            ga0 += step; gb0 += step; ga1 += step; gb1 += step;
            int nb_ = buf ^ 1;
            CP16(sa[nb_], ga0); CP16(sb[nb_], gb0);
            CP16(sa1[nb_], ga1); CP16(sb1[nb_], gb1);
            CPCOMMIT();
        }
#pragma unroll
        for (int kk = 0; kk < G_BK; kk++) {
            float a[8], bb[8];
            *(float4*)&a[0] = *(const float4*)&As[buf][kk][ty * 8];
            *(float4*)&a[4] = *(const float4*)&As[buf][kk][ty * 8 + 4];
            *(float4*)&bb[0] = *(const float4*)&Bs[buf][kk][tx * 8];
            *(float4*)&bb[4] = *(const float4*)&Bs[buf][kk][tx * 8 + 4];
#pragma unroll
            for (int i = 0; i < 8; i++)
#pragma unroll
                for (int j = 0; j < 8; j++) acc[i][j] = fmaf(a[i], bb[j], acc[i][j]);
        }
        if (more) CPWAIT0();
        __syncthreads();
        buf ^= 1;
    }

#pragma unroll
    for (int i = 0; i < 8; i++) {
        float* crow = Cb + (size_t)(m0 + ty * 8 + i) * DD + n0 + tx * 8;
        *(float4*)&crow[0] = *(float4*)&acc[i][0];
        *(float4*)&crow[4] = *(float4*)&acc[i][4];
    }
}

// ---------------- 3) column norms of alpha over d ---------------------------
__global__ __launch_bounds__(256) void colnorm_kernel()
{
    int b = blockIdx.y;
    int e0 = blockIdx.x * 64;
    int el = threadIdx.x & 63;
    int dg = threadIdx.x >> 6;
    const float* A = g_alpha + (size_t)b * DD * DD;
    float s = 0.f;
    for (int d = dg; d < DD; d += 4) {
        float v = A[(size_t)d * DD + e0 + el];
        s = fmaf(v, v, s);
    }
    __shared__ float red[4][64];
    red[dg][el] = s;
    __syncthreads();
    if (dg == 0) {
        float tot = red[0][el] + red[1][el] + red[2][el] + red[3][el];
        g_invn[b * DD + e0 + el] = rsqrtf(fmaxf(tot, EPSF));
    }
}

// ---------------- 4) hmean[b,t,e] = sum_d nb[b,t,d] * alpha[b,d,e] * invn[b,e]
// M=256 (t), N=512 (e), K=512 (d). A is M-major -> staged as [BM][BK].
// cp.async double buffer, 2 CTAs/SM.
__global__ __launch_bounds__(256, 2) void gemm_hmean_kernel()
{
    const int b = blockIdx.z;
    const float* A = g_nb + (size_t)b * TT * DD;       // A[m][k], ld = DD
    const float* Bm = g_alpha + (size_t)b * DD * DD;   // B[k][n], ld = DD
    const float* invn = g_invn + b * DD;
    float* Cb = g_hmean + (size_t)b * TT * DD;

    __shared__ __align__(16) float As[2][G_BM][G_BK];
    __shared__ __align__(16) float Bs[2][G_BK][G_BN];

    const int m0 = blockIdx.y * G_BM;
    const int n0 = blockIdx.x * G_BN;
    const int tid = threadIdx.x;
    const int tx = tid & 15;
    const int ty = tid >> 4;

    // A-tile coords: 128 rows x 16 cols = 512 float4 (4 per row)
    const int amm0 = tid >> 2, akf = tid & 3;
    const int amm1 = (tid + 256) >> 2;
    // B-tile coords
    const int bkk0 = tid >> 5, bmf = tid & 31;
    const int bkk1 = (tid + 256) >> 5;

    const float* gA0 = A + (size_t)(m0 + amm0) * DD + akf * 4;
    const float* gA1 = A + (size_t)(m0 + amm1) * DD + akf * 4;
    const float* gB0 = Bm + (size_t)bkk0 * DD + n0 + bmf * 4;
    const float* gB1 = Bm + (size_t)bkk1 * DD + n0 + bmf * 4;

    unsigned sA0[2], sA1[2], sB0[2], sB1[2];
#pragma unroll
    for (int s = 0; s < 2; s++) {
        sA0[s] = su32(&As[s][amm0][akf * 4]);
        sA1[s] = su32(&As[s][amm1][akf * 4]);
        sB0[s] = su32(&Bs[s][bkk0][bmf * 4]);
        sB1[s] = su32(&Bs[s][bkk1][bmf * 4]);
    }

    float acc[8][8];
#pragma unroll
    for (int i = 0; i < 8; i++)
#pragma unroll
        for (int j = 0; j < 8; j++) acc[i][j] = 0.f;

    // prologue: tile 0 -> buffer 0
    CP16(sA0[0], gA0); CP16(sA1[0], gA1);
    CP16(sB0[0], gB0); CP16(sB1[0], gB1);
    CPCOMMIT();
    CPWAIT0();
    __syncthreads();

    int buf = 0;
    const int stepB = G_BK * DD;
    for (int k0 = 0; k0 < DD; k0 += G_BK) {
        const bool more = (k0 + G_BK) < DD;
        if (more) {
            gA0 += G_BK; gA1 += G_BK; gB0 += stepB; gB1 += stepB;
            int nb_ = buf ^ 1;
            CP16(sA0[nb_], gA0); CP16(sA1[nb_], gA1);
            CP16(sB0[nb_], gB0); CP16(sB1[nb_], gB1);
            CPCOMMIT();
        }
#pragma unroll
        for (int kk = 0; kk < G_BK; kk++) {
            float a[8], bb[8];
#pragma unroll
            for (int i = 0; i < 8; i++) a[i] = As[buf][ty * 8 + i][kk];  // broadcast
            *(float4*)&bb[0] = *(const float4*)&Bs[buf][kk][tx * 8];
            *(float4*)&bb[4] = *(const float4*)&Bs[buf][kk][tx * 8 + 4];
#pragma unroll
            for (int i = 0; i < 8; i++)
#pragma unroll
                for (int j = 0; j < 8; j++) acc[i][j] = fmaf(a[i], bb[j], acc[i][j]);
        }
        if (more) CPWAIT0();
        __syncthreads();
        buf ^= 1;
    }

    float sc[8];
#pragma unroll
    for (int j = 0; j < 8; j++) sc[j] = invn[n0 + tx * 8 + j];
#pragma unroll
    for (int i = 0; i < 8; i++) {
        float out[8];
#pragma unroll
        for (int j = 0; j < 8; j++) out[j] = acc[i][j] * sc[j];
        float* crow = Cb + (size_t)(m0 + ty * 8 + i) * DD + n0 + tx * 8;
        *(float4*)&crow[0] = *(float4*)&out[0];
        *(float4*)&crow[4] = *(float4*)&out[4];
    }
}

// ---------------- 5) perspective matching -----------------------------------
__global__ __launch_bounds__(256) void persp_kernel(
    const float* __restrict__ inp_a, const float* __restrict__ W,
    float* __restrict__ out, int dup)
{
    __shared__ float sW[PP * DD];   // 40 KB
    int tid = threadIdx.x;
    for (int i = tid; i < PP * DD / 4; i += 256)
        ((float4*)sW)[i] = ((const float4*)W)[i];
    __syncthreads();

    int warp = tid >> 5, lane = tid & 31;
    int bt = blockIdx.x * 8 + warp;   // grid = B*T/8 = 1024

    const float* a = inp_a + (size_t)bt * DD;
    const float* h = g_hmean + (size_t)bt * DD;
    float av[16], hv[16];
#pragma unroll
    for (int i = 0; i < 16; i++) {
        av[i] = a[lane + 32 * i];
        hv[i] = h[lane + 32 * i];
    }

    const int n = BB * TT * PP;
    for (int p = 0; p < PP; p++) {
        float s1 = 0.f, s2 = 0.f, s3 = 0.f;
#pragma unroll
        for (int i = 0; i < 16; i++) {
            float w = sW[p * DD + lane + 32 * i];
            float t1 = w * av[i];
            float t2 = w * hv[i];
            s1 = fmaf(t1, t1, s1);
            s2 = fmaf(t2, t2, s2);
            s3 = fmaf(t1, t2, s3);
        }
#pragma unroll
        for (int off = 16; off; off >>= 1) {
            s1 += __shfl_xor_sync(0xffffffffu, s1, off);
            s2 += __shfl_xor_sync(0xffffffffu, s2, off);
            s3 += __shfl_xor_sync(0xffffffffu, s3, off);
        }
        if (lane == 0) {
            float r = s3 * rsqrtf(fmaxf(s1, EPSF)) * rsqrtf(fmaxf(s2, EPSF));
            int idx = bt * PP + p;
            out[idx] = r;
            if (dup) out[idx + n] = r;
        }
    }
}

// ---------------- launch ----------------------------------------------------
extern "C" void kernel_launch(void* const* d_in, const int* in_sizes, int n_in,
                              void* d_out, int out_size)
{
    const float* inp_a = (const float*)d_in[0];
    const float* inp_b = (const float*)d_in[1];
    const float* W = (const float*)d_in[2];
    float* out = (float*)d_out;

    (void)in_sizes; (void)n_in;

    // 1) normalize both inputs
    normalize_kernel<<<2 * BB * TT, 128>>>(inp_a, inp_b);

    // 2) alpha = nb^T @ na (per batch)
    gemm_alpha_kernel<<<dim3(DD / G_BN, DD / G_BM, BB), 256>>>();

    // 3) column inverse norms of alpha
    colnorm_kernel<<<dim3(DD / 64, BB), 256>>>();

    // 4) hmean = nb @ (alpha * invn)
    gemm_hmean_kernel<<<dim3(DD / G_BN, TT / G_BM, BB), 256>>>();

    // 5) perspective outputs (tuple (persp, persp) -> write twice if room)
    int n = BB * TT * PP;
    int dup = (out_size >= 2 * n) ? 1 : 0;
    persp_kernel<<<BB * TT / 8, 256>>>(inp_a, W, out, dup);
}